// round 16
// baseline (speedup 1.0000x reference)
#include <cuda_runtime.h>

#define NB 2
#define NC 128
#define NH 64
#define NW 64
#define NG 8
#define NPIX 4096
#define HP 78
#define PP (78*78)
#define NBORD 1988   // border pixels per padded plane: 2*7*78 + 2*64*7
#define ZB 249       // ceil(NG*NBORD*4 / 256) border-zero blocks per (b, m)

// Plane-per-cq layouts:
//  Q: [(b*NG+g)*4 + cq]*NPIX + pix
//  K/V: [(b*NG+g)*4 + cq]*PP + off   (off = padded-7 coords)
__device__ float4 g_Q[NB*NG*4*NPIX];
__device__ float4 g_K[NB*NG*4*PP];
__device__ float4 g_V[NB*NG*4*PP];

// exp(x) without MUFU: runs entirely on the fma/alu pipes.
// Valid for |x| < ~85 (logits here are within +-60). Rel err ~3e-6.
__device__ __forceinline__ float fexp(float x) {
    float t = x * 1.4426950408889634f;      // log2(e)
    float z = t + 12582912.0f;              // round-to-nearest via magic
    int   i = __float_as_int(z);
    float n = z - 12582912.0f;
    float f = t - n;                        // f in [-0.5, 0.5]
    float p = 1.3333558146e-3f;             // 2^f minimax, deg 5
    p = fmaf(p, f, 9.6181291076e-3f);
    p = fmaf(p, f, 5.5504108664e-2f);
    p = fmaf(p, f, 2.4022650696e-1f);
    p = fmaf(p, f, 6.9314718056e-1f);
    p = fmaf(p, f, 1.0f);
    float s = __int_as_float((i + (127 - 0x4B400000)) << 23);  // 2^n
    return p * s;
}

// One kernel: blocks with bx<64 do the 1x1-conv GEMM; blocks with bx>=64 zero
// the 7-wide halo of the padded K/V planes (disjoint regions -> safe to fuse).
__global__ __launch_bounds__(256) void qkv_kernel(
    const float* __restrict__ fm,
    const float* __restrict__ wq,
    const float* __restrict__ wk,
    const float* __restrict__ wv)
{
    const int m = blockIdx.z;           // 0=Q, 1=K, 2=V
    const int b = blockIdx.y;
    const int bx = blockIdx.x;

    if (bx >= 64) {
        if (m == 0) return;
        int i = (bx - 64)*256 + threadIdx.x;
        if (i >= NG*NBORD*4) return;
        int cq = i & 3;
        int r = i >> 2;
        int bp = r % NBORD;
        int gg = r / NBORD;
        int off;
        if (bp < 546) {
            off = (bp / 78)*HP + (bp % 78);
        } else if (bp < 1092) {
            int q = bp - 546;
            off = (71 + q / 78)*HP + (q % 78);
        } else if (bp < 1540) {
            int q = bp - 1092;
            off = (7 + q / 7)*HP + (q % 7);
        } else {
            int q = bp - 1540;
            off = (7 + q / 7)*HP + 71 + (q % 7);
        }
        int idx = ((b*NG + gg)*4 + cq)*PP + off;
        float4 z = make_float4(0.f, 0.f, 0.f, 0.f);
        if (m == 1) g_K[idx] = z; else g_V[idx] = z;
        return;
    }

    const int pixbase = bx * 64;
    const int tid = threadIdx.x;
    const int p4 = tid & 15;
    const int og = tid >> 4;

    const float* W = (m == 0) ? wq : (m == 1) ? wk : wv;
    const float* xin = fm + ((size_t)b*2*NC + (m == 0 ? NC : 0))*NPIX + pixbase + p4*4;
    const float* Wb = W + og*8*NC;

    float acc[8][4];
    #pragma unroll
    for (int k = 0; k < 8; k++)
        acc[k][0] = acc[k][1] = acc[k][2] = acc[k][3] = 0.f;

    #pragma unroll 2
    for (int c4 = 0; c4 < 32; c4++) {
        float4 xv[4];
        #pragma unroll
        for (int cc = 0; cc < 4; cc++)
            xv[cc] = *reinterpret_cast<const float4*>(xin + (size_t)(c4*4 + cc)*NPIX);
        #pragma unroll
        for (int k = 0; k < 8; k++) {
            float4 w4 = *reinterpret_cast<const float4*>(Wb + k*NC + c4*4);
            acc[k][0] += w4.x*xv[0].x + w4.y*xv[1].x + w4.z*xv[2].x + w4.w*xv[3].x;
            acc[k][1] += w4.x*xv[0].y + w4.y*xv[1].y + w4.z*xv[2].y + w4.w*xv[3].y;
            acc[k][2] += w4.x*xv[0].z + w4.y*xv[1].z + w4.z*xv[2].z + w4.w*xv[3].z;
            acc[k][3] += w4.x*xv[0].w + w4.y*xv[1].w + w4.z*xv[2].w + w4.w*xv[3].w;
        }
    }

    const int o0 = og * 8;
    const int g = o0 >> 4;
    const int cq0 = (o0 & 15) >> 2;
    #pragma unroll
    for (int pi = 0; pi < 4; pi++) {
        int pixel = pixbase + p4*4 + pi;
        float4 v0 = make_float4(acc[0][pi], acc[1][pi], acc[2][pi], acc[3][pi]);
        float4 v1 = make_float4(acc[4][pi], acc[5][pi], acc[6][pi], acc[7][pi]);
        if (m == 0) {
            int base = ((b*NG + g)*4)*NPIX + pixel;
            g_Q[base + cq0*NPIX]       = v0;
            g_Q[base + (cq0 + 1)*NPIX] = v1;
        } else {
            int y = pixel >> 6, x = pixel & 63;
            int off = (y + 7)*HP + (x + 7);
            float4* dst = (m == 1) ? g_K : g_V;
            int base = ((b*NG + g)*4)*PP + off;
            dst[base + cq0*PP]       = v0;
            dst[base + (cq0 + 1)*PP] = v1;
        }
    }
}

// Phase-split attention: one block per (b, g, y) row of 64 pixels.
// Threads 0..63  (warps 0-1, role A): main 7x7 window softmax for pixel x=tid.
// Threads 64..127 (warps 2-3, role B): row+col refine for pixel x=tid-64.
// B writes its normalized 16-ch partial to smem; one __syncthreads; A adds
// and stores. Thin threads (~100 live regs) -> cap 170 regs, 12 warps/SM.
__global__ __launch_bounds__(128, 3) void attn_kernel(
    const float* __restrict__ rel_h,
    const float* __restrict__ rel_w,
    float* __restrict__ out)
{
    __shared__ float smB[64*17];

    const int y = blockIdx.x & 63;
    const int g = (blockIdx.x >> 6) & 7;
    const int b = blockIdx.x >> 9;
    const int bg = b*NG + g;
    const int tid = threadIdx.x;
    const int x = tid & 63;
    const bool isA = tid < 64;
    const int pix = y*NW + x;

    const float4* __restrict__ Qp = g_Q + (size_t)bg*4*NPIX;
    const float4* __restrict__ Kp = g_K + (size_t)bg*4*PP;
    const float4* __restrict__ Vp = g_V + (size_t)bg*4*PP;

    float qa[16];
    #pragma unroll
    for (int cq = 0; cq < 4; cq++) {
        float4 qv = Qp[cq*NPIX + pix];
        qa[cq*4+0] = qv.x; qa[cq*4+1] = qv.y; qa[cq*4+2] = qv.z; qa[cq*4+3] = qv.w;
    }

    float oa[16];
    #pragma unroll
    for (int c = 0; c < 16; c++) oa[c] = 0.f;

    if (!isA) {
        // ===== role B: refine row (phase 0) + col (phase 1), online =====
        #pragma unroll
        for (int phase = 0; phase < 2; phase++) {
            float r[16];
            #pragma unroll
            for (int c = 0; c < 16; c++) r[c] = 0.f;
            float ss = 0.f;
            #pragma unroll
            for (int tp = 0; tp < 15; tp++) {
                int off = (phase == 0) ? ((y + 7)*HP + (x + tp))
                                       : ((y + tp)*HP + (x + 7));
                float4 k0 = Kp[0*PP + off], k1 = Kp[1*PP + off];
                float4 k2 = Kp[2*PP + off], k3 = Kp[3*PP + off];
                float d =
                      qa[0]*k0.x  + qa[1]*k0.y  + qa[2]*k0.z  + qa[3]*k0.w
                    + qa[4]*k1.x  + qa[5]*k1.y  + qa[6]*k1.z  + qa[7]*k1.w
                    + qa[8]*k2.x  + qa[9]*k2.y  + qa[10]*k2.z + qa[11]*k2.w
                    + qa[12]*k3.x + qa[13]*k3.y + qa[14]*k3.z + qa[15]*k3.w;
                float e = fexp(d);
                ss += e;
                float4 v0 = Vp[0*PP + off], v1 = Vp[1*PP + off];
                float4 v2 = Vp[2*PP + off], v3 = Vp[3*PP + off];
                r[0]  += e*v0.x; r[1]  += e*v0.y; r[2]  += e*v0.z; r[3]  += e*v0.w;
                r[4]  += e*v1.x; r[5]  += e*v1.y; r[6]  += e*v1.z; r[7]  += e*v1.w;
                r[8]  += e*v2.x; r[9]  += e*v2.y; r[10] += e*v2.z; r[11] += e*v2.w;
                r[12] += e*v3.x; r[13] += e*v3.y; r[14] += e*v3.z; r[15] += e*v3.w;
            }
            float inv = 1.0f / ss;
            #pragma unroll
            for (int c = 0; c < 16; c++) oa[c] += r[c] * inv;
        }
        #pragma unroll
        for (int c = 0; c < 16; c++) smB[x*17 + c] = oa[c];
    } else {
        // ===== role A: main 7x7 window, fused K+V online raw-exp =====
        const float* rel = (g < 4) ? (rel_h + g*16*7) : (rel_w + (g - 4)*16*7);
        float bias[7];
        #pragma unroll
        for (int i = 0; i < 7; i++) {
            float s = 0.f;
            #pragma unroll
            for (int c = 0; c < 16; c++) s += qa[c] * rel[c*7 + i];
            bias[i] = s;
        }
        const bool useI = (g < 4);

        float ss = 0.f;
        #pragma unroll
        for (int i = 0; i < 7; i++) {
            #pragma unroll
            for (int j = 0; j < 7; j++) {
                int off = (y + 4 + i)*HP + (x + 4 + j);
                float4 k0 = Kp[0*PP + off], k1 = Kp[1*PP + off];
                float4 k2 = Kp[2*PP + off], k3 = Kp[3*PP + off];
                float d = (useI ? bias[i] : bias[j])
                    + qa[0]*k0.x  + qa[1]*k0.y  + qa[2]*k0.z  + qa[3]*k0.w
                    + qa[4]*k1.x  + qa[5]*k1.y  + qa[6]*k1.z  + qa[7]*k1.w
                    + qa[8]*k2.x  + qa[9]*k2.y  + qa[10]*k2.z + qa[11]*k2.w
                    + qa[12]*k3.x + qa[13]*k3.y + qa[14]*k3.z + qa[15]*k3.w;
                float e = fexp(d);
                ss += e;
                float4 v0 = Vp[0*PP + off], v1 = Vp[1*PP + off];
                float4 v2 = Vp[2*PP + off], v3 = Vp[3*PP + off];
                oa[0]  += e*v0.x; oa[1]  += e*v0.y; oa[2]  += e*v0.z; oa[3]  += e*v0.w;
                oa[4]  += e*v1.x; oa[5]  += e*v1.y; oa[6]  += e*v1.z; oa[7]  += e*v1.w;
                oa[8]  += e*v2.x; oa[9]  += e*v2.y; oa[10] += e*v2.z; oa[11] += e*v2.w;
                oa[12] += e*v3.x; oa[13] += e*v3.y; oa[14] += e*v3.z; oa[15] += e*v3.w;
            }
        }
        float inv = 1.0f / ss;
        #pragma unroll
        for (int c = 0; c < 16; c++) oa[c] *= inv;
    }

    __syncthreads();

    if (isA) {
        // merge B's refine partial and store out[b][g*16+c][y][x]
        float* ob = out + ((size_t)b*NC + g*16)*NPIX + pix;
        #pragma unroll
        for (int c = 0; c < 16; c++)
            ob[c*NPIX] = oa[c] + smB[x*17 + c];
    }
}

extern "C" void kernel_launch(void* const* d_in, const int* in_sizes, int n_in,
                              void* d_out, int out_size) {
    const float* fm = (const float*)d_in[0];
    const float* wq = (const float*)d_in[1];
    const float* wk = (const float*)d_in[2];
    const float* wv = (const float*)d_in[3];
    const float* rh = (const float*)d_in[4];
    const float* rw = (const float*)d_in[5];
    float* out = (float*)d_out;

    dim3 grid(64 + ZB, NB, 3);
    qkv_kernel<<<grid, 256>>>(fm, wq, wk, wv);

    attn_kernel<<<NB*NG*NH, 128>>>(rh, rw, out);
}